// round 13
// baseline (speedup 1.0000x reference)
#include <cuda_runtime.h>
#include <cuda_bf16.h>
#include <cstdint>

#define N_NODES 50000
#define N_EDGES 500000
#define HDIM    128
#define H2      256
#define NLAYERS 4
#define NGRAPH  1000
#define MEPS    1e-7f
#define LNEPS   1e-5f
#define SCAN_BLKS 49

// ---------------- scratch ----------------------------------------------------
__device__ float  g_h[(size_t)N_NODES * HDIM];
__device__ float  g_z[(size_t)N_NODES * HDIM];
__device__ float  g_o[(size_t)N_NODES * HDIM];
__device__ float  g_u[(size_t)N_NODES * H2];
__device__ int    g_cnt[N_NODES + 1];
__device__ int    g_ptr[N_NODES + 1];
__device__ int    g_cur[N_NODES];
__device__ int    g_ssrc[N_EDGES];
__device__ float4 g_sattr[N_EDGES];
__device__ int    g_gcnt[NGRAPH + 1];
__device__ int    g_gptr[NGRAPH + 1];
__device__ int    g_bsum[64];
__device__ int    g_boff[64];

// ---------------- f32x2 helpers -----------------------------------------------
__device__ __forceinline__ unsigned long long fma2(unsigned long long a,
                                                   unsigned long long b,
                                                   unsigned long long c) {
    unsigned long long d;
    asm("fma.rn.f32x2 %0, %1, %2, %3;" : "=l"(d) : "l"(a), "l"(b), "l"(c));
    return d;
}
__device__ __forceinline__ unsigned long long dup2(float a) {
    unsigned long long d;
    asm("mov.b64 %0, {%1, %1};" : "=l"(d) : "f"(a));
    return d;
}
__device__ __forceinline__ float2 unpack2(unsigned long long v) {
    float2 r;
    asm("mov.b64 {%0, %1}, %2;" : "=f"(r.x), "=f"(r.y) : "l"(v));
    return r;
}

// ---------------- prep --------------------------------------------------------
__global__ void k_zero() {
    int i = blockIdx.x * blockDim.x + threadIdx.x;
    if (i <= N_NODES) g_cnt[i] = 0;
    if (i <= NGRAPH) g_gcnt[i] = 0;
}
__global__ void k_hist_dst(const int* __restrict__ ei) {
    int e = blockIdx.x * blockDim.x + threadIdx.x;
    if (e < N_EDGES) atomicAdd(&g_cnt[ei[N_EDGES + e]], 1);
}
__global__ void k_hist_batch(const int* __restrict__ batch) {
    int i = blockIdx.x * blockDim.x + threadIdx.x;
    if (i < N_NODES) atomicAdd(&g_gcnt[batch[i]], 1);
}
__device__ __forceinline__ int blk_scan(int v, int* ws) {
    int lane = threadIdx.x & 31, w = threadIdx.x >> 5;
    int val = v;
#pragma unroll
    for (int o = 1; o < 32; o <<= 1) { int u = __shfl_up_sync(0xffffffffu, val, o); if (lane >= o) val += u; }
    if (lane == 31) ws[w] = val;
    __syncthreads();
    if (w == 0) {
        int s = ws[lane];
#pragma unroll
        for (int o = 1; o < 32; o <<= 1) { int u = __shfl_up_sync(0xffffffffu, s, o); if (lane >= o) s += u; }
        ws[lane] = s;
    }
    __syncthreads();
    return val + (w ? ws[w - 1] : 0);
}
__global__ void k_scan1() {
    __shared__ int ws[32];
    int i = blockIdx.x * 1024 + threadIdx.x;
    int v = (i < N_NODES) ? g_cnt[i] : 0;
    int incl = blk_scan(v, ws);
    if (i < N_NODES) g_ptr[i] = incl - v;
    if (threadIdx.x == 1023) g_bsum[blockIdx.x] = incl;
}
__global__ void k_scan2() {
    __shared__ int ws[32];
    int t = threadIdx.x;
    int v = (t < SCAN_BLKS) ? g_bsum[t] : 0;
    int incl = blk_scan(v, ws);
    if (t < SCAN_BLKS) g_boff[t] = incl - v;
    __syncthreads();
    int gv = (t < NGRAPH) ? g_gcnt[t] : 0;
    int gincl = blk_scan(gv, ws);
    if (t < NGRAPH) g_gptr[t] = gincl - gv;
    if (t == 0) g_gptr[NGRAPH] = N_NODES;
}
__global__ void k_scan3() {
    int i = blockIdx.x * 1024 + threadIdx.x;
    if (i < N_NODES) {
        int p = g_ptr[i] + g_boff[blockIdx.x];
        g_ptr[i] = p;
        g_cur[i] = p;
    }
    if (i == 0) g_ptr[N_NODES] = N_EDGES;
}
__global__ void k_scatter(const int* __restrict__ ei, const float* __restrict__ ea) {
    int e = blockIdx.x * blockDim.x + threadIdx.x;
    if (e >= N_EDGES) return;
    int d = ei[N_EDGES + e];
    int pos = atomicAdd(&g_cur[d], 1);
    g_ssrc[pos] = ei[e];
    g_sattr[pos] = make_float4(ea[3 * e], ea[3 * e + 1], ea[3 * e + 2], 0.f);
}

// ---------------- node encoder ------------------------------------------------
__global__ void k_encode(const float* __restrict__ x, const float* __restrict__ W,
                         const float* __restrict__ b) {
    __shared__ float4 sW[9][32];
    __shared__ float4 sb[32];
    int tid = threadIdx.x;
    for (int i = tid; i < 9 * 32; i += blockDim.x)
        sW[i / 32][i % 32] = *(const float4*)&W[(i / 32) * HDIM + (i % 32) * 4];
    if (tid < 32) sb[tid] = *(const float4*)&b[tid * 4];
    __syncthreads();
    int gw = (blockIdx.x * blockDim.x + tid) >> 5;
    if (gw >= N_NODES) return;
    int lane = tid & 31;
    const float* xr = x + gw * 9;
    float xv[9];
#pragma unroll
    for (int k = 0; k < 9; k++) xv[k] = __ldg(&xr[k]);
    float4 acc = sb[lane];
#pragma unroll
    for (int k = 0; k < 9; k++) {
        float4 w = sW[k][lane];
        acc.x += xv[k] * w.x; acc.y += xv[k] * w.y;
        acc.z += xv[k] * w.z; acc.w += xv[k] * w.w;
    }
    ((float4*)g_h)[gw * 32 + lane] = acc;
}

// ---------------- edge softmax-aggregation (warp per node, unroll 2) ----------
__device__ __forceinline__ void edge_acc(float4 hv, float4 a, float4 w0, float4 w1,
                                         float4 w2, float4 wb, float tv,
                                         float4& den, float4& num) {
    float m, e;
    m = fmaxf(hv.x + wb.x + a.x * w0.x + a.y * w1.x + a.z * w2.x, 0.f) + MEPS;
    e = __expf(tv * m); den.x += e; num.x += e * m;
    m = fmaxf(hv.y + wb.y + a.x * w0.y + a.y * w1.y + a.z * w2.y, 0.f) + MEPS;
    e = __expf(tv * m); den.y += e; num.y += e * m;
    m = fmaxf(hv.z + wb.z + a.x * w0.z + a.y * w1.z + a.z * w2.z, 0.f) + MEPS;
    e = __expf(tv * m); den.z += e; num.z += e * m;
    m = fmaxf(hv.w + wb.w + a.x * w0.w + a.y * w1.w + a.z * w2.w, 0.f) + MEPS;
    e = __expf(tv * m); den.w += e; num.w += e * m;
}
__global__ void __launch_bounds__(256) k_edge(const float* __restrict__ eW,
                                              const float* __restrict__ eb,
                                              const float* __restrict__ tall,
                                              int layer, int use_z) {
    __shared__ float4 sw[4][32];
    int tid = threadIdx.x;
    if (tid < 32) {
        sw[0][tid] = *(const float4*)&eW[0 * HDIM + tid * 4];
        sw[1][tid] = *(const float4*)&eW[1 * HDIM + tid * 4];
        sw[2][tid] = *(const float4*)&eW[2 * HDIM + tid * 4];
        sw[3][tid] = *(const float4*)&eb[tid * 4];
    }
    __syncthreads();
    int gw = (blockIdx.x * blockDim.x + tid) >> 5;
    if (gw >= N_NODES) return;
    int lane = tid & 31;
    const float4* zp = (const float4*)(use_z ? g_z : g_h);
    float tv = __ldg(&tall[layer]);
    int j0 = __ldg(&g_ptr[gw]), j1 = __ldg(&g_ptr[gw + 1]);
    float4 w0 = sw[0][lane], w1 = sw[1][lane], w2 = sw[2][lane], wb = sw[3][lane];
    float4 den = make_float4(0.f, 0.f, 0.f, 0.f);
    float4 num = make_float4(0.f, 0.f, 0.f, 0.f);
    int j = j0;
    for (; j + 1 < j1; j += 2) {
        int s0 = __ldg(&g_ssrc[j]);
        int s1 = __ldg(&g_ssrc[j + 1]);
        float4 a0 = __ldg(&g_sattr[j]);
        float4 a1 = __ldg(&g_sattr[j + 1]);
        float4 h0 = __ldg(&zp[s0 * 32 + lane]);
        float4 h1 = __ldg(&zp[s1 * 32 + lane]);
        edge_acc(h0, a0, w0, w1, w2, wb, tv, den, num);
        edge_acc(h1, a1, w0, w1, w2, wb, tv, den, num);
    }
    if (j < j1) {
        int s0 = __ldg(&g_ssrc[j]);
        float4 a0 = __ldg(&g_sattr[j]);
        float4 h0 = __ldg(&zp[s0 * 32 + lane]);
        edge_acc(h0, a0, w0, w1, w2, wb, tv, den, num);
    }
    float4 hz = zp[gw * 32 + lane];
    float4 o;
    if (j1 > j0) {
        o.x = num.x / den.x + hz.x;
        o.y = num.y / den.y + hz.y;
        o.z = num.z / den.z + hz.z;
        o.w = num.w / den.w + hz.w;
    } else {
        o = hz;
    }
    ((float4*)g_o)[gw * 32 + lane] = o;
}

// ---------------- GEMM1: u = relu(LN(g_o @ W1 + b1)) --------------------------
// BM=64, BN=256, BK=16, double-buffered, vectorized smem access.
__global__ void __launch_bounds__(256) k_gemm1(const float* __restrict__ B,
                                               const float* __restrict__ bias,
                                               const float* __restrict__ lg,
                                               const float* __restrict__ lb) {
    __shared__ float As[2][16][68];
    __shared__ float Bs[2][16][256];
    int tid = threadIdx.x;
    int tx = tid & 31, ty = tid >> 5;
    int row0 = blockIdx.x * 64;
    int am = tid >> 2, ak = (tid & 3) * 4;
    int bn4 = tid & 63, bk0 = tid >> 6;
    unsigned long long acc[8][4];
#pragma unroll
    for (int i = 0; i < 8; i++)
#pragma unroll
        for (int j = 0; j < 4; j++) acc[i][j] = 0ull;

    {
        int r = row0 + am;
        float4 va = (r < N_NODES) ? *(const float4*)&g_o[(size_t)r * HDIM + ak]
                                  : make_float4(0.f, 0.f, 0.f, 0.f);
        As[0][ak + 0][am] = va.x; As[0][ak + 1][am] = va.y;
        As[0][ak + 2][am] = va.z; As[0][ak + 3][am] = va.w;
#pragma unroll
        for (int l = 0; l < 4; l++) {
            int bk = bk0 + l * 4;
            *(float4*)&Bs[0][bk][bn4 * 4] = __ldg((const float4*)&B[(size_t)bk * H2 + bn4 * 4]);
        }
    }
    __syncthreads();

    for (int it = 0; it < 8; it++) {
        int cur = it & 1;
        float4 va;
        float4 vb[4];
        if (it < 7) {
            int kkn = (it + 1) * 16;
            int r = row0 + am;
            va = (r < N_NODES) ? *(const float4*)&g_o[(size_t)r * HDIM + kkn + ak]
                               : make_float4(0.f, 0.f, 0.f, 0.f);
#pragma unroll
            for (int l = 0; l < 4; l++) {
                int bk = bk0 + l * 4;
                vb[l] = __ldg((const float4*)&B[(size_t)(kkn + bk) * H2 + bn4 * 4]);
            }
        }
#pragma unroll
        for (int k = 0; k < 16; k++) {
            ulonglong2 b01 = *(const ulonglong2*)&Bs[cur][k][tx * 4];
            ulonglong2 b23 = *(const ulonglong2*)&Bs[cur][k][128 + tx * 4];
            float4 a03 = *(const float4*)&As[cur][k][ty * 8];
            float4 a47 = *(const float4*)&As[cur][k][ty * 8 + 4];
            float av[8] = {a03.x, a03.y, a03.z, a03.w, a47.x, a47.y, a47.z, a47.w};
#pragma unroll
            for (int i = 0; i < 8; i++) {
                unsigned long long a2 = dup2(av[i]);
                acc[i][0] = fma2(a2, b01.x, acc[i][0]);
                acc[i][1] = fma2(a2, b01.y, acc[i][1]);
                acc[i][2] = fma2(a2, b23.x, acc[i][2]);
                acc[i][3] = fma2(a2, b23.y, acc[i][3]);
            }
        }
        if (it < 7) {
            int nb = cur ^ 1;
            As[nb][ak + 0][am] = va.x; As[nb][ak + 1][am] = va.y;
            As[nb][ak + 2][am] = va.z; As[nb][ak + 3][am] = va.w;
#pragma unroll
            for (int l = 0; l < 4; l++) {
                int bk = bk0 + l * 4;
                *(float4*)&Bs[nb][bk][bn4 * 4] = vb[l];
            }
            __syncthreads();
        }
    }

    float4 bia0 = __ldg((const float4*)&bias[tx * 4]);
    float4 bia1 = __ldg((const float4*)&bias[128 + tx * 4]);
    float4 gv0 = __ldg((const float4*)&lg[tx * 4]);
    float4 gv1 = __ldg((const float4*)&lg[128 + tx * 4]);
    float4 bv0 = __ldg((const float4*)&lb[tx * 4]);
    float4 bv1 = __ldg((const float4*)&lb[128 + tx * 4]);
#pragma unroll
    for (int i = 0; i < 8; i++) {
        float v[8];
        float2 p;
        p = unpack2(acc[i][0]); v[0] = p.x + bia0.x; v[1] = p.y + bia0.y;
        p = unpack2(acc[i][1]); v[2] = p.x + bia0.z; v[3] = p.y + bia0.w;
        p = unpack2(acc[i][2]); v[4] = p.x + bia1.x; v[5] = p.y + bia1.y;
        p = unpack2(acc[i][3]); v[6] = p.x + bia1.z; v[7] = p.y + bia1.w;
        float s = 0.f;
#pragma unroll
        for (int j = 0; j < 8; j++) s += v[j];
#pragma unroll
        for (int o = 16; o > 0; o >>= 1) s += __shfl_xor_sync(0xffffffffu, s, o);
        float mean = s * (1.f / 256.f);
        float q = 0.f;
#pragma unroll
        for (int j = 0; j < 8; j++) { float d = v[j] - mean; q += d * d; }
#pragma unroll
        for (int o = 16; o > 0; o >>= 1) q += __shfl_xor_sync(0xffffffffu, q, o);
        float rstd = rsqrtf(q * (1.f / 256.f) + LNEPS);
        int r = row0 + ty * 8 + i;
        if (r < N_NODES) {
            float4 o0, o1;
            o0.x = fmaxf((v[0] - mean) * rstd * gv0.x + bv0.x, 0.f);
            o0.y = fmaxf((v[1] - mean) * rstd * gv0.y + bv0.y, 0.f);
            o0.z = fmaxf((v[2] - mean) * rstd * gv0.z + bv0.z, 0.f);
            o0.w = fmaxf((v[3] - mean) * rstd * gv0.w + bv0.w, 0.f);
            o1.x = fmaxf((v[4] - mean) * rstd * gv1.x + bv1.x, 0.f);
            o1.y = fmaxf((v[5] - mean) * rstd * gv1.y + bv1.y, 0.f);
            o1.z = fmaxf((v[6] - mean) * rstd * gv1.z + bv1.z, 0.f);
            o1.w = fmaxf((v[7] - mean) * rstd * gv1.w + bv1.w, 0.f);
            *(float4*)&g_u[(size_t)r * H2 + tx * 4] = o0;
            *(float4*)&g_u[(size_t)r * H2 + 128 + tx * 4] = o1;
        }
    }
}

// ---------------- GEMM2 + fused residual + next-layer LN ----------------------
// BM=64, BN=128, BK=16, double-buffered, 256 thr, 8x4/thread; 782 blocks.
__global__ void __launch_bounds__(256) k_gemm2(const float* __restrict__ B,
                                               const float* __restrict__ bias,
                                               const float* __restrict__ nlg,
                                               const float* __restrict__ nlb,
                                               int first) {
    __shared__ float As[2][16][68];
    __shared__ float Bs[2][16][128];
    int tid = threadIdx.x;
    int tx = tid & 31, ty = tid >> 5;
    int row0 = blockIdx.x * 64;
    int am = tid >> 2, ak = (tid & 3) * 4;
    unsigned long long acc[8][2];
#pragma unroll
    for (int i = 0; i < 8; i++) { acc[i][0] = 0ull; acc[i][1] = 0ull; }

    {
        int r = row0 + am;
        float4 va = (r < N_NODES) ? *(const float4*)&g_u[(size_t)r * H2 + ak]
                                  : make_float4(0.f, 0.f, 0.f, 0.f);
        As[0][ak + 0][am] = va.x; As[0][ak + 1][am] = va.y;
        As[0][ak + 2][am] = va.z; As[0][ak + 3][am] = va.w;
#pragma unroll
        for (int l = 0; l < 2; l++) {
            int idx = tid + l * 256;
            int bk = idx >> 5, bn4 = idx & 31;
            *(float4*)&Bs[0][bk][bn4 * 4] = __ldg((const float4*)&B[(size_t)bk * HDIM + bn4 * 4]);
        }
    }
    __syncthreads();

    for (int it = 0; it < 16; it++) {
        int cur = it & 1;
        float4 va, vb[2];
        if (it < 15) {
            int kkn = (it + 1) * 16;
            int r = row0 + am;
            va = (r < N_NODES) ? *(const float4*)&g_u[(size_t)r * H2 + kkn + ak]
                               : make_float4(0.f, 0.f, 0.f, 0.f);
#pragma unroll
            for (int l = 0; l < 2; l++) {
                int idx = tid + l * 256;
                int bk = idx >> 5, bn4 = idx & 31;
                vb[l] = __ldg((const float4*)&B[(size_t)(kkn + bk) * HDIM + bn4 * 4]);
            }
        }
#pragma unroll
        for (int k = 0; k < 16; k++) {
            unsigned long long b0 = *(const unsigned long long*)&Bs[cur][k][tx * 2];
            unsigned long long b1 = *(const unsigned long long*)&Bs[cur][k][64 + tx * 2];
            float4 a03 = *(const float4*)&As[cur][k][ty * 8];
            float4 a47 = *(const float4*)&As[cur][k][ty * 8 + 4];
            float av[8] = {a03.x, a03.y, a03.z, a03.w, a47.x, a47.y, a47.z, a47.w};
#pragma unroll
            for (int i = 0; i < 8; i++) {
                unsigned long long a2 = dup2(av[i]);
                acc[i][0] = fma2(a2, b0, acc[i][0]);
                acc[i][1] = fma2(a2, b1, acc[i][1]);
            }
        }
        if (it < 15) {
            int nb = cur ^ 1;
            As[nb][ak + 0][am] = va.x; As[nb][ak + 1][am] = va.y;
            As[nb][ak + 2][am] = va.z; As[nb][ak + 3][am] = va.w;
#pragma unroll
            for (int l = 0; l < 2; l++) {
                int idx = tid + l * 256;
                int bk = idx >> 5, bn4 = idx & 31;
                *(float4*)&Bs[nb][bk][bn4 * 4] = vb[l];
            }
            __syncthreads();
        }
    }

    int c0 = tx * 2, c1 = 64 + tx * 2;
    float2 bia0 = __ldg((const float2*)&bias[c0]);
    float2 bia1 = __ldg((const float2*)&bias[c1]);
    float2 gg0 = __ldg((const float2*)&nlg[c0]);
    float2 gg1 = __ldg((const float2*)&nlg[c1]);
    float2 cb0 = __ldg((const float2*)&nlb[c0]);
    float2 cb1 = __ldg((const float2*)&nlb[c1]);
#pragma unroll
    for (int i = 0; i < 8; i++) {
        int r = row0 + ty * 8 + i;     // uniform across warp
        bool ok = (r < N_NODES);
        float2 y0 = unpack2(acc[i][0]);
        float2 y1 = unpack2(acc[i][1]);
        y0.x += bia0.x; y0.y += bia0.y;
        y1.x += bia1.x; y1.y += bia1.y;
        float* hp = &g_h[(size_t)r * HDIM];
        if (!first && ok) {
            float2 h0 = *(float2*)&hp[c0];
            float2 h1 = *(float2*)&hp[c1];
            y0.x += h0.x; y0.y += h0.y;
            y1.x += h1.x; y1.y += h1.y;
        }
        if (ok) {
            *(float2*)&hp[c0] = y0;
            *(float2*)&hp[c1] = y1;
        }
        float s = y0.x + y0.y + y1.x + y1.y;
#pragma unroll
        for (int o = 16; o > 0; o >>= 1) s += __shfl_xor_sync(0xffffffffu, s, o);
        float mean = s * (1.f / 128.f);
        float q = (y0.x - mean) * (y0.x - mean) + (y0.y - mean) * (y0.y - mean)
                + (y1.x - mean) * (y1.x - mean) + (y1.y - mean) * (y1.y - mean);
#pragma unroll
        for (int o = 16; o > 0; o >>= 1) q += __shfl_xor_sync(0xffffffffu, q, o);
        float rstd = rsqrtf(q * (1.f / 128.f) + LNEPS);
        if (ok) {
            float2 z0, z1;
            z0.x = fmaxf((y0.x - mean) * rstd * gg0.x + cb0.x, 0.f);
            z0.y = fmaxf((y0.y - mean) * rstd * gg0.y + cb0.y, 0.f);
            z1.x = fmaxf((y1.x - mean) * rstd * gg1.x + cb1.x, 0.f);
            z1.y = fmaxf((y1.y - mean) * rstd * gg1.y + cb1.y, 0.f);
            float* zp = &g_z[(size_t)r * HDIM];
            *(float2*)&zp[c0] = z0;
            *(float2*)&zp[c1] = z1;
        }
    }
}

// ---------------- mean pool ---------------------------------------------------
__global__ void k_pool(float* __restrict__ out) {
    int g = blockIdx.x, c = threadIdx.x;
    int s = g_gptr[g], e = g_gptr[g + 1];
    float acc = 0.f;
    for (int i = s; i < e; i++) acc += g_z[(size_t)i * HDIM + c];
    out[g * HDIM + c] = (e > s) ? acc / (float)(e - s) : 0.f;
}

// ---------------- launch ------------------------------------------------------
extern "C" void kernel_launch(void* const* d_in, const int* in_sizes, int n_in,
                              void* d_out, int out_size) {
    (void)in_sizes; (void)n_in; (void)out_size;
    const float* x     = (const float*)d_in[0];
    const int*   ei    = (const int*)d_in[1];
    const float* eattr = (const float*)d_in[2];
    const int*   batch = (const int*)d_in[3];
    const float* encW  = (const float*)d_in[4];
    const float* encb  = (const float*)d_in[5];
    const float* eW    = (const float*)d_in[6];
    const float* eb    = (const float*)d_in[7];
    const float* lng   = (const float*)d_in[8];
    const float* lnb   = (const float*)d_in[9];
    const float* W1    = (const float*)d_in[10];
    const float* b1    = (const float*)d_in[11];
    const float* mg    = (const float*)d_in[12];
    const float* mb    = (const float*)d_in[13];
    const float* W2    = (const float*)d_in[14];
    const float* b2    = (const float*)d_in[15];
    const float* tptr  = (const float*)d_in[16];
    float* out = (float*)d_out;

    const int NWBLK = (N_NODES * 32 + 255) / 256;

    k_zero<<<(N_NODES + 256) / 256, 256>>>();
    k_hist_dst<<<(N_EDGES + 255) / 256, 256>>>(ei);
    k_hist_batch<<<(N_NODES + 255) / 256, 256>>>(batch);
    k_scan1<<<SCAN_BLKS, 1024>>>();
    k_scan2<<<1, 1024>>>();
    k_scan3<<<SCAN_BLKS, 1024>>>();
    k_scatter<<<(N_EDGES + 255) / 256, 256>>>(ei, eattr);

    k_encode<<<NWBLK, 256>>>(x, encW, encb);

    for (int i = 0; i < NLAYERS; i++) {
        k_edge<<<NWBLK, 256>>>(eW, eb, tptr, i, (i > 0) ? 1 : 0);
        k_gemm1<<<(N_NODES + 63) / 64, 256>>>(W1 + (size_t)i * HDIM * H2,
                                              b1 + (size_t)i * H2,
                                              mg + (size_t)i * H2,
                                              mb + (size_t)i * H2);
        int nl = (i + 1 < NLAYERS) ? (i + 1) : 0;
        k_gemm2<<<(N_NODES + 63) / 64, 256>>>(W2 + (size_t)i * H2 * HDIM,
                                              b2 + (size_t)i * HDIM,
                                              lng + (size_t)nl * HDIM,
                                              lnb + (size_t)nl * HDIM,
                                              (i == 0) ? 1 : 0);
    }

    k_pool<<<NGRAPH, HDIM>>>(out);
}

// round 14
// speedup vs baseline: 1.0467x; 1.0467x over previous
#include <cuda_runtime.h>
#include <cuda_bf16.h>
#include <cstdint>

#define N_NODES 50000
#define N_EDGES 500000
#define HDIM    128
#define H2      256
#define NLAYERS 4
#define NGRAPH  1000
#define MEPS    1e-7f
#define LNEPS   1e-5f
#define SCAN_BLKS 49

// ---------------- scratch ----------------------------------------------------
__device__ float  g_h[(size_t)N_NODES * HDIM];
__device__ float  g_z[(size_t)N_NODES * HDIM];
__device__ float  g_o[(size_t)N_NODES * HDIM];
__device__ float  g_u[(size_t)N_NODES * H2];
__device__ int    g_cnt[N_NODES + 1];
__device__ int    g_ptr[N_NODES + 1];
__device__ int    g_cur[N_NODES];
__device__ int    g_ssrc[N_EDGES];
__device__ float4 g_sattr[N_EDGES];
__device__ int    g_gcnt[NGRAPH + 1];
__device__ int    g_gptr[NGRAPH + 1];
__device__ int    g_bsum[64];
__device__ int    g_boff[64];

// ---------------- f32x2 helpers -----------------------------------------------
__device__ __forceinline__ unsigned long long fma2(unsigned long long a,
                                                   unsigned long long b,
                                                   unsigned long long c) {
    unsigned long long d;
    asm("fma.rn.f32x2 %0, %1, %2, %3;" : "=l"(d) : "l"(a), "l"(b), "l"(c));
    return d;
}
__device__ __forceinline__ unsigned long long dup2(float a) {
    unsigned long long d;
    asm("mov.b64 %0, {%1, %1};" : "=l"(d) : "f"(a));
    return d;
}
__device__ __forceinline__ float2 unpack2(unsigned long long v) {
    float2 r;
    asm("mov.b64 {%0, %1}, %2;" : "=f"(r.x), "=f"(r.y) : "l"(v));
    return r;
}

// ---------------- prep --------------------------------------------------------
__global__ void k_zero() {
    int i = blockIdx.x * blockDim.x + threadIdx.x;
    if (i <= N_NODES) g_cnt[i] = 0;
    if (i <= NGRAPH) g_gcnt[i] = 0;
}
__global__ void k_hist_dst(const int* __restrict__ ei) {
    int e = blockIdx.x * blockDim.x + threadIdx.x;
    if (e < N_EDGES) atomicAdd(&g_cnt[ei[N_EDGES + e]], 1);
}
__global__ void k_hist_batch(const int* __restrict__ batch) {
    int i = blockIdx.x * blockDim.x + threadIdx.x;
    if (i < N_NODES) atomicAdd(&g_gcnt[batch[i]], 1);
}
__device__ __forceinline__ int blk_scan(int v, int* ws) {
    int lane = threadIdx.x & 31, w = threadIdx.x >> 5;
    int val = v;
#pragma unroll
    for (int o = 1; o < 32; o <<= 1) { int u = __shfl_up_sync(0xffffffffu, val, o); if (lane >= o) val += u; }
    if (lane == 31) ws[w] = val;
    __syncthreads();
    if (w == 0) {
        int s = ws[lane];
#pragma unroll
        for (int o = 1; o < 32; o <<= 1) { int u = __shfl_up_sync(0xffffffffu, s, o); if (lane >= o) s += u; }
        ws[lane] = s;
    }
    __syncthreads();
    return val + (w ? ws[w - 1] : 0);
}
__global__ void k_scan1() {
    __shared__ int ws[32];
    int i = blockIdx.x * 1024 + threadIdx.x;
    int v = (i < N_NODES) ? g_cnt[i] : 0;
    int incl = blk_scan(v, ws);
    if (i < N_NODES) g_ptr[i] = incl - v;
    if (threadIdx.x == 1023) g_bsum[blockIdx.x] = incl;
}
__global__ void k_scan2() {
    __shared__ int ws[32];
    int t = threadIdx.x;
    int v = (t < SCAN_BLKS) ? g_bsum[t] : 0;
    int incl = blk_scan(v, ws);
    if (t < SCAN_BLKS) g_boff[t] = incl - v;
    __syncthreads();
    int gv = (t < NGRAPH) ? g_gcnt[t] : 0;
    int gincl = blk_scan(gv, ws);
    if (t < NGRAPH) g_gptr[t] = gincl - gv;
    if (t == 0) g_gptr[NGRAPH] = N_NODES;
}
__global__ void k_scan3() {
    int i = blockIdx.x * 1024 + threadIdx.x;
    if (i < N_NODES) {
        int p = g_ptr[i] + g_boff[blockIdx.x];
        g_ptr[i] = p;
        g_cur[i] = p;
    }
    if (i == 0) g_ptr[N_NODES] = N_EDGES;
}
__global__ void k_scatter(const int* __restrict__ ei, const float* __restrict__ ea) {
    int e = blockIdx.x * blockDim.x + threadIdx.x;
    if (e >= N_EDGES) return;
    int d = ei[N_EDGES + e];
    int pos = atomicAdd(&g_cur[d], 1);
    g_ssrc[pos] = ei[e];
    g_sattr[pos] = make_float4(ea[3 * e], ea[3 * e + 1], ea[3 * e + 2], 0.f);
}

// ---------------- node encoder ------------------------------------------------
__global__ void k_encode(const float* __restrict__ x, const float* __restrict__ W,
                         const float* __restrict__ b) {
    __shared__ float4 sW[9][32];
    __shared__ float4 sb[32];
    int tid = threadIdx.x;
    for (int i = tid; i < 9 * 32; i += blockDim.x)
        sW[i / 32][i % 32] = *(const float4*)&W[(i / 32) * HDIM + (i % 32) * 4];
    if (tid < 32) sb[tid] = *(const float4*)&b[tid * 4];
    __syncthreads();
    int gw = (blockIdx.x * blockDim.x + tid) >> 5;
    if (gw >= N_NODES) return;
    int lane = tid & 31;
    const float* xr = x + gw * 9;
    float xv[9];
#pragma unroll
    for (int k = 0; k < 9; k++) xv[k] = __ldg(&xr[k]);
    float4 acc = sb[lane];
#pragma unroll
    for (int k = 0; k < 9; k++) {
        float4 w = sW[k][lane];
        acc.x += xv[k] * w.x; acc.y += xv[k] * w.y;
        acc.z += xv[k] * w.z; acc.w += xv[k] * w.w;
    }
    ((float4*)g_h)[gw * 32 + lane] = acc;
}

// ---------------- edge softmax-aggregation (warp per node, unroll 2) ----------
__device__ __forceinline__ void edge_acc(float4 hv, float4 a, float4 w0, float4 w1,
                                         float4 w2, float4 wb, float tv,
                                         float4& den, float4& num) {
    float m, e;
    m = fmaxf(hv.x + wb.x + a.x * w0.x + a.y * w1.x + a.z * w2.x, 0.f) + MEPS;
    e = __expf(tv * m); den.x += e; num.x += e * m;
    m = fmaxf(hv.y + wb.y + a.x * w0.y + a.y * w1.y + a.z * w2.y, 0.f) + MEPS;
    e = __expf(tv * m); den.y += e; num.y += e * m;
    m = fmaxf(hv.z + wb.z + a.x * w0.z + a.y * w1.z + a.z * w2.z, 0.f) + MEPS;
    e = __expf(tv * m); den.z += e; num.z += e * m;
    m = fmaxf(hv.w + wb.w + a.x * w0.w + a.y * w1.w + a.z * w2.w, 0.f) + MEPS;
    e = __expf(tv * m); den.w += e; num.w += e * m;
}
__global__ void __launch_bounds__(256) k_edge(const float* __restrict__ eW,
                                              const float* __restrict__ eb,
                                              const float* __restrict__ tall,
                                              int layer, int use_z) {
    __shared__ float4 sw[4][32];
    int tid = threadIdx.x;
    if (tid < 32) {
        sw[0][tid] = *(const float4*)&eW[0 * HDIM + tid * 4];
        sw[1][tid] = *(const float4*)&eW[1 * HDIM + tid * 4];
        sw[2][tid] = *(const float4*)&eW[2 * HDIM + tid * 4];
        sw[3][tid] = *(const float4*)&eb[tid * 4];
    }
    __syncthreads();
    int gw = (blockIdx.x * blockDim.x + tid) >> 5;
    if (gw >= N_NODES) return;
    int lane = tid & 31;
    const float4* zp = (const float4*)(use_z ? g_z : g_h);
    float tv = __ldg(&tall[layer]);
    int j0 = __ldg(&g_ptr[gw]), j1 = __ldg(&g_ptr[gw + 1]);
    float4 w0 = sw[0][lane], w1 = sw[1][lane], w2 = sw[2][lane], wb = sw[3][lane];
    float4 den = make_float4(0.f, 0.f, 0.f, 0.f);
    float4 num = make_float4(0.f, 0.f, 0.f, 0.f);
    int j = j0;
    for (; j + 1 < j1; j += 2) {
        int s0 = __ldg(&g_ssrc[j]);
        int s1 = __ldg(&g_ssrc[j + 1]);
        float4 a0 = __ldg(&g_sattr[j]);
        float4 a1 = __ldg(&g_sattr[j + 1]);
        float4 h0 = __ldg(&zp[s0 * 32 + lane]);
        float4 h1 = __ldg(&zp[s1 * 32 + lane]);
        edge_acc(h0, a0, w0, w1, w2, wb, tv, den, num);
        edge_acc(h1, a1, w0, w1, w2, wb, tv, den, num);
    }
    if (j < j1) {
        int s0 = __ldg(&g_ssrc[j]);
        float4 a0 = __ldg(&g_sattr[j]);
        float4 h0 = __ldg(&zp[s0 * 32 + lane]);
        edge_acc(h0, a0, w0, w1, w2, wb, tv, den, num);
    }
    float4 hz = zp[gw * 32 + lane];
    float4 o;
    if (j1 > j0) {
        o.x = num.x / den.x + hz.x;
        o.y = num.y / den.y + hz.y;
        o.z = num.z / den.z + hz.z;
        o.w = num.w / den.w + hz.w;
    } else {
        o = hz;
    }
    ((float4*)g_o)[gw * 32 + lane] = o;
}

// ---------------- GEMM1: u = relu(LN(g_o @ W1 + b1)) --------------------------
// BM=64, BN=256, BK=16, double-buffered (exact R12 shape).
__global__ void __launch_bounds__(256) k_gemm1(const float* __restrict__ B,
                                               const float* __restrict__ bias,
                                               const float* __restrict__ lg,
                                               const float* __restrict__ lb) {
    __shared__ float As[2][16][65];
    __shared__ float Bs[2][16][256];
    int tid = threadIdx.x;
    int tx = tid & 31, ty = tid >> 5;
    int row0 = blockIdx.x * 64;
    int am = tid >> 2, ak = (tid & 3) * 4;
    int bn4 = tid & 63, bk0 = tid >> 6;
    unsigned long long acc[8][4];
#pragma unroll
    for (int i = 0; i < 8; i++)
#pragma unroll
        for (int j = 0; j < 4; j++) acc[i][j] = 0ull;

    {
        int r = row0 + am;
        float4 va = (r < N_NODES) ? *(const float4*)&g_o[(size_t)r * HDIM + ak]
                                  : make_float4(0.f, 0.f, 0.f, 0.f);
        As[0][ak + 0][am] = va.x; As[0][ak + 1][am] = va.y;
        As[0][ak + 2][am] = va.z; As[0][ak + 3][am] = va.w;
#pragma unroll
        for (int l = 0; l < 4; l++) {
            int bk = bk0 + l * 4;
            *(float4*)&Bs[0][bk][bn4 * 4] = __ldg((const float4*)&B[(size_t)bk * H2 + bn4 * 4]);
        }
    }
    __syncthreads();

    for (int it = 0; it < 8; it++) {
        int cur = it & 1;
        float4 va;
        float4 vb[4];
        if (it < 7) {
            int kkn = (it + 1) * 16;
            int r = row0 + am;
            va = (r < N_NODES) ? *(const float4*)&g_o[(size_t)r * HDIM + kkn + ak]
                               : make_float4(0.f, 0.f, 0.f, 0.f);
#pragma unroll
            for (int l = 0; l < 4; l++) {
                int bk = bk0 + l * 4;
                vb[l] = __ldg((const float4*)&B[(size_t)(kkn + bk) * H2 + bn4 * 4]);
            }
        }
#pragma unroll
        for (int k = 0; k < 16; k++) {
            unsigned long long bv[4];
            bv[0] = *(const unsigned long long*)&Bs[cur][k][tx * 4];
            bv[1] = *(const unsigned long long*)&Bs[cur][k][tx * 4 + 2];
            bv[2] = *(const unsigned long long*)&Bs[cur][k][128 + tx * 4];
            bv[3] = *(const unsigned long long*)&Bs[cur][k][128 + tx * 4 + 2];
#pragma unroll
            for (int i = 0; i < 8; i++) {
                unsigned long long a2 = dup2(As[cur][k][ty * 8 + i]);
#pragma unroll
                for (int j = 0; j < 4; j++) acc[i][j] = fma2(a2, bv[j], acc[i][j]);
            }
        }
        if (it < 7) {
            int nb = cur ^ 1;
            As[nb][ak + 0][am] = va.x; As[nb][ak + 1][am] = va.y;
            As[nb][ak + 2][am] = va.z; As[nb][ak + 3][am] = va.w;
#pragma unroll
            for (int l = 0; l < 4; l++) {
                int bk = bk0 + l * 4;
                *(float4*)&Bs[nb][bk][bn4 * 4] = vb[l];
            }
            __syncthreads();
        }
    }

    float4 bia0 = __ldg((const float4*)&bias[tx * 4]);
    float4 bia1 = __ldg((const float4*)&bias[128 + tx * 4]);
    float4 gv0 = __ldg((const float4*)&lg[tx * 4]);
    float4 gv1 = __ldg((const float4*)&lg[128 + tx * 4]);
    float4 bv0 = __ldg((const float4*)&lb[tx * 4]);
    float4 bv1 = __ldg((const float4*)&lb[128 + tx * 4]);
#pragma unroll
    for (int i = 0; i < 8; i++) {
        float v[8];
        float2 p;
        p = unpack2(acc[i][0]); v[0] = p.x + bia0.x; v[1] = p.y + bia0.y;
        p = unpack2(acc[i][1]); v[2] = p.x + bia0.z; v[3] = p.y + bia0.w;
        p = unpack2(acc[i][2]); v[4] = p.x + bia1.x; v[5] = p.y + bia1.y;
        p = unpack2(acc[i][3]); v[6] = p.x + bia1.z; v[7] = p.y + bia1.w;
        float s = 0.f;
#pragma unroll
        for (int j = 0; j < 8; j++) s += v[j];
#pragma unroll
        for (int o = 16; o > 0; o >>= 1) s += __shfl_xor_sync(0xffffffffu, s, o);
        float mean = s * (1.f / 256.f);
        float q = 0.f;
#pragma unroll
        for (int j = 0; j < 8; j++) { float d = v[j] - mean; q += d * d; }
#pragma unroll
        for (int o = 16; o > 0; o >>= 1) q += __shfl_xor_sync(0xffffffffu, q, o);
        float rstd = rsqrtf(q * (1.f / 256.f) + LNEPS);
        int r = row0 + ty * 8 + i;
        if (r < N_NODES) {
            float4 o0, o1;
            o0.x = fmaxf((v[0] - mean) * rstd * gv0.x + bv0.x, 0.f);
            o0.y = fmaxf((v[1] - mean) * rstd * gv0.y + bv0.y, 0.f);
            o0.z = fmaxf((v[2] - mean) * rstd * gv0.z + bv0.z, 0.f);
            o0.w = fmaxf((v[3] - mean) * rstd * gv0.w + bv0.w, 0.f);
            o1.x = fmaxf((v[4] - mean) * rstd * gv1.x + bv1.x, 0.f);
            o1.y = fmaxf((v[5] - mean) * rstd * gv1.y + bv1.y, 0.f);
            o1.z = fmaxf((v[6] - mean) * rstd * gv1.z + bv1.z, 0.f);
            o1.w = fmaxf((v[7] - mean) * rstd * gv1.w + bv1.w, 0.f);
            *(float4*)&g_u[(size_t)r * H2 + tx * 4] = o0;
            *(float4*)&g_u[(size_t)r * H2 + 128 + tx * 4] = o1;
        }
    }
}

// ---------------- GEMM2 + fused next-layer LN (exact R12 shape) ---------------
// BM=128, BN=128, BK=16, double-buffered; writes g_h (raw) and g_z = relu(LN(h)).
__global__ void __launch_bounds__(256) k_gemm2(const float* __restrict__ B,
                                               const float* __restrict__ bias,
                                               const float* __restrict__ nlg,
                                               const float* __restrict__ nlb,
                                               int first) {
    __shared__ float As[2][16][129];
    __shared__ float Bs[2][16][128];
    int tid = threadIdx.x;
    int tx = tid & 15, ty = tid >> 4;
    int row0 = blockIdx.x * 128;
    unsigned long long acc[8][4];
#pragma unroll
    for (int i = 0; i < 8; i++)
#pragma unroll
        for (int j = 0; j < 4; j++) acc[i][j] = 0ull;

#pragma unroll
    for (int l = 0; l < 2; l++) {
        int idx = tid + l * 256;
        int m = idx >> 2, k4 = (idx & 3) * 4;
        int r = row0 + m;
        float4 va = (r < N_NODES) ? *(const float4*)&g_u[(size_t)r * H2 + k4]
                                  : make_float4(0.f, 0.f, 0.f, 0.f);
        As[0][k4 + 0][m] = va.x; As[0][k4 + 1][m] = va.y;
        As[0][k4 + 2][m] = va.z; As[0][k4 + 3][m] = va.w;
        int bk = idx >> 5, bn4 = idx & 31;
        *(float4*)&Bs[0][bk][bn4 * 4] = __ldg((const float4*)&B[(size_t)bk * HDIM + bn4 * 4]);
    }
    __syncthreads();

    for (int it = 0; it < 16; it++) {
        int cur = it & 1;
        float4 va[2], vb[2];
        if (it < 15) {
            int kkn = (it + 1) * 16;
#pragma unroll
            for (int l = 0; l < 2; l++) {
                int idx = tid + l * 256;
                int m = idx >> 2, k4 = (idx & 3) * 4;
                int r = row0 + m;
                va[l] = (r < N_NODES) ? *(const float4*)&g_u[(size_t)r * H2 + kkn + k4]
                                      : make_float4(0.f, 0.f, 0.f, 0.f);
                int bk = idx >> 5, bn4 = idx & 31;
                vb[l] = __ldg((const float4*)&B[(size_t)(kkn + bk) * HDIM + bn4 * 4]);
            }
        }
#pragma unroll
        for (int k = 0; k < 16; k++) {
            unsigned long long bv[4];
            bv[0] = *(const unsigned long long*)&Bs[cur][k][tx * 4];
            bv[1] = *(const unsigned long long*)&Bs[cur][k][tx * 4 + 2];
            bv[2] = *(const unsigned long long*)&Bs[cur][k][64 + tx * 4];
            bv[3] = *(const unsigned long long*)&Bs[cur][k][64 + tx * 4 + 2];
#pragma unroll
            for (int i = 0; i < 8; i++) {
                unsigned long long a2 = dup2(As[cur][k][ty * 8 + i]);
#pragma unroll
                for (int j = 0; j < 4; j++) acc[i][j] = fma2(a2, bv[j], acc[i][j]);
            }
        }
        if (it < 15) {
            int nb = cur ^ 1;
#pragma unroll
            for (int l = 0; l < 2; l++) {
                int idx = tid + l * 256;
                int m = idx >> 2, k4 = (idx & 3) * 4;
                As[nb][k4 + 0][m] = va[l].x; As[nb][k4 + 1][m] = va[l].y;
                As[nb][k4 + 2][m] = va[l].z; As[nb][k4 + 3][m] = va[l].w;
                int bk = idx >> 5, bn4 = idx & 31;
                *(float4*)&Bs[nb][bk][bn4 * 4] = vb[l];
            }
            __syncthreads();
        }
    }

    float4 bia0 = __ldg((const float4*)&bias[tx * 4]);
    float4 bia1 = __ldg((const float4*)&bias[64 + tx * 4]);
    float4 gg0 = __ldg((const float4*)&nlg[tx * 4]);
    float4 gg1 = __ldg((const float4*)&nlg[64 + tx * 4]);
    float4 cb0 = __ldg((const float4*)&nlb[tx * 4]);
    float4 cb1 = __ldg((const float4*)&nlb[64 + tx * 4]);
#pragma unroll
    for (int i = 0; i < 8; i++) {
        int r = row0 + ty * 8 + i;
        bool ok = (r < N_NODES);
        float2 p;
        float4 y0, y1;
        p = unpack2(acc[i][0]); y0.x = p.x + bia0.x; y0.y = p.y + bia0.y;
        p = unpack2(acc[i][1]); y0.z = p.x + bia0.z; y0.w = p.y + bia0.w;
        p = unpack2(acc[i][2]); y1.x = p.x + bia1.x; y1.y = p.y + bia1.y;
        p = unpack2(acc[i][3]); y1.z = p.x + bia1.z; y1.w = p.y + bia1.w;
        float* hp = &g_h[(size_t)r * HDIM];
        if (!first && ok) {
            float4 h0 = *(float4*)&hp[tx * 4];
            float4 h1 = *(float4*)&hp[64 + tx * 4];
            y0.x += h0.x; y0.y += h0.y; y0.z += h0.z; y0.w += h0.w;
            y1.x += h1.x; y1.y += h1.y; y1.z += h1.z; y1.w += h1.w;
        }
        if (ok) {
            *(float4*)&hp[tx * 4] = y0;
            *(float4*)&hp[64 + tx * 4] = y1;
        }
        float s = y0.x + y0.y + y0.z + y0.w + y1.x + y1.y + y1.z + y1.w;
#pragma unroll
        for (int o = 8; o > 0; o >>= 1) s += __shfl_xor_sync(0xffffffffu, s, o);
        float mean = s * (1.f / 128.f);
        float q = 0.f;
        q += (y0.x - mean) * (y0.x - mean) + (y0.y - mean) * (y0.y - mean);
        q += (y0.z - mean) * (y0.z - mean) + (y0.w - mean) * (y0.w - mean);
        q += (y1.x - mean) * (y1.x - mean) + (y1.y - mean) * (y1.y - mean);
        q += (y1.z - mean) * (y1.z - mean) + (y1.w - mean) * (y1.w - mean);
#pragma unroll
        for (int o = 8; o > 0; o >>= 1) q += __shfl_xor_sync(0xffffffffu, q, o);
        float rstd = rsqrtf(q * (1.f / 128.f) + LNEPS);
        if (ok) {
            float4 z0, z1;
            z0.x = fmaxf((y0.x - mean) * rstd * gg0.x + cb0.x, 0.f);
            z0.y = fmaxf((y0.y - mean) * rstd * gg0.y + cb0.y, 0.f);
            z0.z = fmaxf((y0.z - mean) * rstd * gg0.z + cb0.z, 0.f);
            z0.w = fmaxf((y0.w - mean) * rstd * gg0.w + cb0.w, 0.f);
            z1.x = fmaxf((y1.x - mean) * rstd * gg1.x + cb1.x, 0.f);
            z1.y = fmaxf((y1.y - mean) * rstd * gg1.y + cb1.y, 0.f);
            z1.z = fmaxf((y1.z - mean) * rstd * gg1.z + cb1.z, 0.f);
            z1.w = fmaxf((y1.w - mean) * rstd * gg1.w + cb1.w, 0.f);
            float* zp = &g_z[(size_t)r * HDIM];
            *(float4*)&zp[tx * 4] = z0;
            *(float4*)&zp[64 + tx * 4] = z1;
        }
    }
}

// ---------------- mean pool ---------------------------------------------------
__global__ void k_pool(float* __restrict__ out) {
    int g = blockIdx.x, c = threadIdx.x;
    int s = g_gptr[g], e = g_gptr[g + 1];
    float acc = 0.f;
    for (int i = s; i < e; i++) acc += g_z[(size_t)i * HDIM + c];
    out[g * HDIM + c] = (e > s) ? acc / (float)(e - s) : 0.f;
}

// ---------------- launch ------------------------------------------------------
extern "C" void kernel_launch(void* const* d_in, const int* in_sizes, int n_in,
                              void* d_out, int out_size) {
    (void)in_sizes; (void)n_in; (void)out_size;
    const float* x     = (const float*)d_in[0];
    const int*   ei    = (const int*)d_in[1];
    const float* eattr = (const float*)d_in[2];
    const int*   batch = (const int*)d_in[3];
    const float* encW  = (const float*)d_in[4];
    const float* encb  = (const float*)d_in[5];
    const float* eW    = (const float*)d_in[6];
    const float* eb    = (const float*)d_in[7];
    const float* lng   = (const float*)d_in[8];
    const float* lnb   = (const float*)d_in[9];
    const float* W1    = (const float*)d_in[10];
    const float* b1    = (const float*)d_in[11];
    const float* mg    = (const float*)d_in[12];
    const float* mb    = (const float*)d_in[13];
    const float* W2    = (const float*)d_in[14];
    const float* b2    = (const float*)d_in[15];
    const float* tptr  = (const float*)d_in[16];
    float* out = (float*)d_out;

    const int NWBLK = (N_NODES * 32 + 255) / 256;

    k_zero<<<(N_NODES + 256) / 256, 256>>>();
    k_hist_dst<<<(N_EDGES + 255) / 256, 256>>>(ei);
    k_hist_batch<<<(N_NODES + 255) / 256, 256>>>(batch);
    k_scan1<<<SCAN_BLKS, 1024>>>();
    k_scan2<<<1, 1024>>>();
    k_scan3<<<SCAN_BLKS, 1024>>>();
    k_scatter<<<(N_EDGES + 255) / 256, 256>>>(ei, eattr);

    k_encode<<<NWBLK, 256>>>(x, encW, encb);

    for (int i = 0; i < NLAYERS; i++) {
        k_edge<<<NWBLK, 256>>>(eW, eb, tptr, i, (i > 0) ? 1 : 0);
        k_gemm1<<<(N_NODES + 63) / 64, 256>>>(W1 + (size_t)i * HDIM * H2,
                                              b1 + (size_t)i * H2,
                                              mg + (size_t)i * H2,
                                              mb + (size_t)i * H2);
        int nl = (i + 1 < NLAYERS) ? (i + 1) : 0;
        k_gemm2<<<(N_NODES + 127) / 128, 256>>>(W2 + (size_t)i * H2 * HDIM,
                                                b2 + (size_t)i * HDIM,
                                                lng + (size_t)nl * HDIM,
                                                lnb + (size_t)nl * HDIM,
                                                (i == 0) ? 1 : 0);
    }

    k_pool<<<NGRAPH, HDIM>>>(out);
}